// round 3
// baseline (speedup 1.0000x reference)
#include <cuda_runtime.h>
#include <cuda_bf16.h>
#include <math.h>

// Problem constants: B=2, S=2048, D=2048, H=16, Dh=128
#define BB 2
#define SS 2048
#define DD 2048
#define HH 16
#define DH 128
#define MM (BB*SS)          // 4096 rows for the projection GEMMs

// ---------------------------------------------------------------------------
// Scratch (device globals — allocation-free per harness rules)
// ---------------------------------------------------------------------------
__device__ float g_Q[BB*SS*DD];    // Q projection, [B*S, D] row-major
__device__ float g_ctx[BB*SS*DD];  // attention context, [B*S, D] row-major

// ---------------------------------------------------------------------------
// GEMM: C[M,N] = A[M,K] @ W[K,N] + bias[N]
// M=4096, N=2048, K=2048. 128x128 block tile, BK=8, 256 threads, 8x8/thread.
// mode 0: C row-major.  mode 1: head-transposed store into [B,H,S,Dh].
// ---------------------------------------------------------------------------
#define GBM 128
#define GBN 128
#define GBK 8

__global__ __launch_bounds__(256, 2)
void mhsa_gemm_kernel(const float* __restrict__ A, const float* __restrict__ W,
                      const float* __restrict__ bias, float* __restrict__ C,
                      int mode)
{
    const int N = DD, K = DD;
    __shared__ float As[GBK][GBM];   // A stored transposed: As[k][m]
    __shared__ float Bs[GBK][GBN];

    const int tid = threadIdx.x;
    const int bm = blockIdx.y * GBM;
    const int bn = blockIdx.x * GBN;
    const int tx = tid & 15;
    const int ty = tid >> 4;

    // A tile load mapping: one float4 per thread
    const int arow = tid >> 1;
    const int acol = (tid & 1) * 4;
    // B tile load mapping
    const int brow = tid >> 5;
    const int bcol = (tid & 31) * 4;

    float acc[8][8];
#pragma unroll
    for (int i = 0; i < 8; i++)
#pragma unroll
        for (int j = 0; j < 8; j++) acc[i][j] = 0.f;

    const float* Aptr = A + (size_t)(bm + arow) * K + acol;
    const float* Wptr = W + (size_t)brow * N + (bn + bcol);

    for (int k0 = 0; k0 < K; k0 += GBK) {
        float4 av = *(const float4*)Aptr;
        As[acol + 0][arow] = av.x;
        As[acol + 1][arow] = av.y;
        As[acol + 2][arow] = av.z;
        As[acol + 3][arow] = av.w;
        *(float4*)&Bs[brow][bcol] = *(const float4*)Wptr;
        __syncthreads();

#pragma unroll
        for (int kk = 0; kk < GBK; kk++) {
            float a[8], b[8];
            *(float4*)&a[0] = *(const float4*)&As[kk][ty * 4];
            *(float4*)&a[4] = *(const float4*)&As[kk][64 + ty * 4];
            *(float4*)&b[0] = *(const float4*)&Bs[kk][tx * 4];
            *(float4*)&b[4] = *(const float4*)&Bs[kk][64 + tx * 4];
#pragma unroll
            for (int i = 0; i < 8; i++)
#pragma unroll
                for (int j = 0; j < 8; j++)
                    acc[i][j] = fmaf(a[i], b[j], acc[i][j]);
        }
        __syncthreads();
        Aptr += GBK;
        Wptr += (size_t)GBK * N;
    }

    // Epilogue
#pragma unroll
    for (int i = 0; i < 8; i++) {
        int ri = (i < 4) ? (ty * 4 + i) : (64 + ty * 4 + (i - 4));
        int row = bm + ri;
#pragma unroll
        for (int j = 0; j < 8; j++) {
            int cj = (j < 4) ? (tx * 4 + j) : (64 + tx * 4 + (j - 4));
            int col = bn + cj;
            float v = acc[i][j] + bias[col];
            if (mode == 0) {
                C[(size_t)row * N + col] = v;
            } else {
                int b_ = row >> 11;        // / S
                int s_ = row & (SS - 1);
                int h_ = col >> 7;         // / Dh
                int d_ = col & (DH - 1);
                C[(size_t)(((b_ * HH + h_) * SS) + s_) * DH + d_] = v;
            }
        }
    }
}

// ---------------------------------------------------------------------------
// Causal flash attention. One CTA per (qblock, h, b).
// BQ=64 queries, BKV=64 keys per iteration, Dh=128, fp32.
// 256 threads: tx=tid&15, ty=tid>>4. S tile: 4x4/thread. ctx: 4 rows x 8 cols.
// Smem (dynamic, 114944 B): Qst[128][64], Kst[128][64] (d-major), Vs[64][128],
// Pt[64][65] (P transposed, padded).
// ---------------------------------------------------------------------------
#define BQ 64
#define BKV 64
#define ATT_SMEM_FLOATS (8192 + 8192 + 8192 + 64*65)
#define ATT_SMEM_BYTES  (ATT_SMEM_FLOATS * 4)

__global__ __launch_bounds__(256, 1)
void mhsa_attn_kernel(const float* __restrict__ Q, const float* __restrict__ K,
                      const float* __restrict__ V, float* __restrict__ ctxout)
{
    extern __shared__ float sm[];
    float* Qst = sm;              // [128][64]  Qst[d*64 + q]
    float* Kst = sm + 8192;       // [128][64]
    float* Vs  = sm + 16384;      // [64][128]
    float* Pt  = sm + 24576;      // [64][65]   Pt[k*65 + q]

    const int qb = blockIdx.x;
    const int h  = blockIdx.y;
    const int b  = blockIdx.z;
    const int tid = threadIdx.x;
    const int tx = tid & 15;
    const int ty = tid >> 4;
    const int lq  = tid & 31;          // q/k index for transposed loads (warp-spread)
    const int ld4 = (tid >> 5) * 4;    // d base

    // ---- Load Q tile transposed: Qst[d][q] ----
    const float* Qbase = Q + (size_t)(b * SS + qb * BQ) * DD + h * DH;
#pragma unroll
    for (int qh = 0; qh < 2; qh++)
#pragma unroll
        for (int dh = 0; dh < 4; dh++) {
            int q = qh * 32 + lq;
            int d = dh * 32 + ld4;
            float4 v = *(const float4*)(Qbase + (size_t)q * DD + d);
            Qst[(d + 0) * 64 + q] = v.x;
            Qst[(d + 1) * 64 + q] = v.y;
            Qst[(d + 2) * 64 + q] = v.z;
            Qst[(d + 3) * 64 + q] = v.w;
        }

    float ctx[4][8];
    float m[4], l[4];
#pragma unroll
    for (int i = 0; i < 4; i++) {
        m[i] = -INFINITY; l[i] = 0.f;
#pragma unroll
        for (int j = 0; j < 8; j++) ctx[i][j] = 0.f;
    }

    const float scale = 0.08838834764831845f;  // 1/sqrt(128)
    const float* Kbh = K + (size_t)((b * HH + h) * SS) * DH;
    const float* Vbh = V + (size_t)((b * HH + h) * SS) * DH;

    for (int kb = 0; kb <= qb; kb++) {
        __syncthreads();   // previous iteration's PV reads done before overwrite
        const float* Kb = Kbh + (size_t)kb * BKV * DH;
        const float* Vb = Vbh + (size_t)kb * BKV * DH;
        // K transposed load: Kst[d][k]
#pragma unroll
        for (int qh = 0; qh < 2; qh++)
#pragma unroll
            for (int dh = 0; dh < 4; dh++) {
                int k = qh * 32 + lq;
                int d = dh * 32 + ld4;
                float4 v = *(const float4*)(Kb + (size_t)k * DH + d);
                Kst[(d + 0) * 64 + k] = v.x;
                Kst[(d + 1) * 64 + k] = v.y;
                Kst[(d + 2) * 64 + k] = v.z;
                Kst[(d + 3) * 64 + k] = v.w;
            }
        // V row-major load (coalesced)
#pragma unroll
        for (int it = 0; it < 8; it++) {
            int idx = it * 256 + tid;
            ((float4*)Vs)[idx] = ((const float4*)Vb)[idx];
        }
        __syncthreads();

        // ---- S = Q K^T (4x4 per thread) ----
        float s4[4][4];
#pragma unroll
        for (int i = 0; i < 4; i++)
#pragma unroll
            for (int j = 0; j < 4; j++) s4[i][j] = 0.f;
#pragma unroll 4
        for (int d = 0; d < DH; d++) {
            float a[4], bb[4];
            *(float4*)a  = *(const float4*)&Qst[d * 64 + ty * 4];
            *(float4*)bb = *(const float4*)&Kst[d * 64 + tx * 4];
#pragma unroll
            for (int i = 0; i < 4; i++)
#pragma unroll
                for (int j = 0; j < 4; j++)
                    s4[i][j] = fmaf(a[i], bb[j], s4[i][j]);
        }

        // ---- online softmax ----
        const bool diag = (kb == qb);
#pragma unroll
        for (int i = 0; i < 4; i++) {
            int qg = qb * BQ + ty * 4 + i;
            float rm = -INFINITY;
#pragma unroll
            for (int j = 0; j < 4; j++) {
                float v = s4[i][j] * scale;
                if (diag) {
                    int kg = kb * BKV + tx * 4 + j;
                    if (kg > qg) v = -INFINITY;
                }
                s4[i][j] = v;
                rm = fmaxf(rm, v);
            }
#pragma unroll
            for (int off = 1; off < 16; off <<= 1)
                rm = fmaxf(rm, __shfl_xor_sync(0xffffffffu, rm, off));
            float mnew = fmaxf(m[i], rm);
            float alpha = __expf(m[i] - mnew);
            float rs = 0.f;
#pragma unroll
            for (int j = 0; j < 4; j++) {
                float p = __expf(s4[i][j] - mnew);
                s4[i][j] = p;
                rs += p;
            }
#pragma unroll
            for (int off = 1; off < 16; off <<= 1)
                rs += __shfl_xor_sync(0xffffffffu, rs, off);
            l[i] = l[i] * alpha + rs;
            m[i] = mnew;
#pragma unroll
            for (int j = 0; j < 8; j++) ctx[i][j] *= alpha;
#pragma unroll
            for (int j = 0; j < 4; j++)
                Pt[(tx * 4 + j) * 65 + ty * 4 + i] = s4[i][j];
        }
        __syncthreads();

        // ---- ctx += P @ V ----
#pragma unroll 2
        for (int k = 0; k < BKV; k++) {
            float a[4];
#pragma unroll
            for (int i = 0; i < 4; i++) a[i] = Pt[k * 65 + ty * 4 + i];
            float b0[4], b1[4];
            *(float4*)b0 = *(const float4*)&Vs[k * 128 + tx * 4];
            *(float4*)b1 = *(const float4*)&Vs[k * 128 + 64 + tx * 4];
#pragma unroll
            for (int i = 0; i < 4; i++) {
#pragma unroll
                for (int j = 0; j < 4; j++) {
                    ctx[i][j]     = fmaf(a[i], b0[j], ctx[i][j]);
                    ctx[i][4 + j] = fmaf(a[i], b1[j], ctx[i][4 + j]);
                }
            }
        }
    }

    // ---- epilogue: normalize and write [B*S, D] ----
#pragma unroll
    for (int i = 0; i < 4; i++) {
        float inv = 1.f / l[i];
        int qg = qb * BQ + ty * 4 + i;
        float* dst = ctxout + (size_t)(b * SS + qg) * DD + h * DH;
        float4 o0, o1;
        o0.x = ctx[i][0] * inv; o0.y = ctx[i][1] * inv;
        o0.z = ctx[i][2] * inv; o0.w = ctx[i][3] * inv;
        o1.x = ctx[i][4] * inv; o1.y = ctx[i][5] * inv;
        o1.z = ctx[i][6] * inv; o1.w = ctx[i][7] * inv;
        *(float4*)(dst + tx * 4)      = o0;
        *(float4*)(dst + 64 + tx * 4) = o1;
    }
}

// ---------------------------------------------------------------------------
// Residual add + LayerNorm: y = attn_out + x; ln = gamma*(y-mu)*rsqrt(var+eps)+beta
// One CTA (256 threads) per row of D=2048.
// ---------------------------------------------------------------------------
__global__ __launch_bounds__(256)
void mhsa_add_ln_kernel(const float* __restrict__ x, const float* __restrict__ ao,
                        const float* __restrict__ gamma, const float* __restrict__ beta,
                        float* __restrict__ ln)
{
    const int row = blockIdx.x;
    const int tid = threadIdx.x;
    const float4* xr = (const float4*)(x + (size_t)row * DD);
    const float4* ar = (const float4*)(ao + (size_t)row * DD);

    float4 y0, y1;
    {
        float4 xv = xr[tid], av = ar[tid];
        y0 = make_float4(xv.x + av.x, xv.y + av.y, xv.z + av.z, xv.w + av.w);
        xv = xr[tid + 256]; av = ar[tid + 256];
        y1 = make_float4(xv.x + av.x, xv.y + av.y, xv.z + av.z, xv.w + av.w);
    }
    float s  = y0.x + y0.y + y0.z + y0.w + y1.x + y1.y + y1.z + y1.w;
    float sq = y0.x*y0.x + y0.y*y0.y + y0.z*y0.z + y0.w*y0.w
             + y1.x*y1.x + y1.y*y1.y + y1.z*y1.z + y1.w*y1.w;

#pragma unroll
    for (int off = 16; off; off >>= 1) {
        s  += __shfl_xor_sync(0xffffffffu, s,  off);
        sq += __shfl_xor_sync(0xffffffffu, sq, off);
    }
    __shared__ float shs[8], shq[8];
    __shared__ float stats[2];
    int w = tid >> 5, lane = tid & 31;
    if (lane == 0) { shs[w] = s; shq[w] = sq; }
    __syncthreads();
    if (tid == 0) {
        float ts = 0.f, tq = 0.f;
#pragma unroll
        for (int i = 0; i < 8; i++) { ts += shs[i]; tq += shq[i]; }
        float mu = ts / (float)DD;
        float var = tq / (float)DD - mu * mu;
        stats[0] = mu;
        stats[1] = rsqrtf(var + 1e-5f);
    }
    __syncthreads();
    float mu = stats[0], rinv = stats[1];

    const float4* g4 = (const float4*)gamma;
    const float4* b4 = (const float4*)beta;
    float4* lr = (float4*)(ln + (size_t)row * DD);
    {
        float4 gv = g4[tid], bv = b4[tid];
        float4 o = make_float4(gv.x * (y0.x - mu) * rinv + bv.x,
                               gv.y * (y0.y - mu) * rinv + bv.y,
                               gv.z * (y0.z - mu) * rinv + bv.z,
                               gv.w * (y0.w - mu) * rinv + bv.w);
        lr[tid] = o;
        gv = g4[tid + 256]; bv = b4[tid + 256];
        o = make_float4(gv.x * (y1.x - mu) * rinv + bv.x,
                        gv.y * (y1.y - mu) * rinv + bv.y,
                        gv.z * (y1.z - mu) * rinv + bv.z,
                        gv.w * (y1.w - mu) * rinv + bv.w);
        lr[tid + 256] = o;
    }
}

// ---------------------------------------------------------------------------
// Launch: inputs (metadata order): x, Wq, bq, Wk, bk, Wv, bv, Wo, bo, gamma,
// beta, num_heads. Output tuple (ln, attn_out, k, v) flattened into d_out.
// ---------------------------------------------------------------------------
extern "C" void kernel_launch(void* const* d_in, const int* in_sizes, int n_in,
                              void* d_out, int out_size)
{
    const float* x     = (const float*)d_in[0];
    const float* Wq    = (const float*)d_in[1];
    const float* bq    = (const float*)d_in[2];
    const float* Wk    = (const float*)d_in[3];
    const float* bk    = (const float*)d_in[4];
    const float* Wv    = (const float*)d_in[5];
    const float* bv    = (const float*)d_in[6];
    const float* Wo    = (const float*)d_in[7];
    const float* bo    = (const float*)d_in[8];
    const float* gamma = (const float*)d_in[9];
    const float* beta  = (const float*)d_in[10];

    float* out      = (float*)d_out;
    const size_t SEC = (size_t)BB * SS * DD;   // 8388608
    float* out_ln   = out;
    float* out_ao   = out + SEC;
    float* out_k    = out + 2 * SEC;
    float* out_v    = out + 3 * SEC;

    float* qptr = nullptr;
    float* cptr = nullptr;
    cudaGetSymbolAddress((void**)&qptr, g_Q);
    cudaGetSymbolAddress((void**)&cptr, g_ctx);

    cudaFuncSetAttribute(mhsa_attn_kernel,
                         cudaFuncAttributeMaxDynamicSharedMemorySize,
                         ATT_SMEM_BYTES);

    dim3 ggrid(DD / GBN, MM / GBM);   // (16, 32)

    // Projections: Q -> scratch (row-major), K/V -> output slots ([B,H,S,Dh])
    mhsa_gemm_kernel<<<ggrid, 256>>>(x, Wq, bq, qptr, 0);
    mhsa_gemm_kernel<<<ggrid, 256>>>(x, Wk, bk, out_k, 1);
    mhsa_gemm_kernel<<<ggrid, 256>>>(x, Wv, bv, out_v, 1);

    // Flash attention (reads K/V from the output slots — they ARE the k,v outputs)
    dim3 agrid(SS / BQ, HH, BB);      // (32, 16, 2)
    mhsa_attn_kernel<<<agrid, 256, ATT_SMEM_BYTES>>>(qptr, out_k, out_v, cptr);

    // Output projection
    mhsa_gemm_kernel<<<ggrid, 256>>>(cptr, Wo, bo, out_ao, 0);

    // Residual + LayerNorm
    mhsa_add_ln_kernel<<<MM, 256>>>(x, out_ao, gamma, beta, out_ln);
}